// round 1
// baseline (speedup 1.0000x reference)
#include <cuda_runtime.h>

#define HD 64

static const int N_CAP = 100000;
static const int G_CAP = 256;

// Scratch (allocation-free: __device__ globals)
__device__ float g_agg1[N_CAP];
__device__ float g_aggA[N_CAP * HD];
__device__ float g_aggB[N_CAP * HD];
__device__ float g_h1[N_CAP * HD];
__device__ float g_h2[N_CAP * HD];
__device__ float g_sums[G_CAP * HD];
__device__ float g_cnt[G_CAP];

__device__ __forceinline__ void red_add_v4(float* p, float4 v) {
    asm volatile("red.global.add.v4.f32 [%0], {%1,%2,%3,%4};"
                 :: "l"(p), "f"(v.x), "f"(v.y), "f"(v.z), "f"(v.w) : "memory");
}

// ---------------- zero scratch ----------------
__global__ void zero_kernel(int n, int g) {
    int i = blockIdx.x * blockDim.x + threadIdx.x;
    int stride = gridDim.x * blockDim.x;
    float4 z = make_float4(0.f, 0.f, 0.f, 0.f);
    int nv = n * (HD / 4);
    float4* a4 = (float4*)g_aggA;
    float4* b4 = (float4*)g_aggB;
    for (int k = i; k < nv; k += stride) { a4[k] = z; b4[k] = z; }
    for (int k = i; k < n; k += stride) g_agg1[k] = 0.f;
    int sv = g * (HD / 4);
    float4* s4 = (float4*)g_sums;
    for (int k = i; k < sv; k += stride) s4[k] = z;
    for (int k = i; k < g; k += stride) g_cnt[k] = 0.f;
}

// ---------------- layer 1: scalar scatter (C_IN = 1) ----------------
__global__ void scatter1_kernel(const int* __restrict__ src, const int* __restrict__ dst,
                                const float* __restrict__ ew, const float* __restrict__ x, int E) {
    int e = blockIdx.x * blockDim.x + threadIdx.x;
    if (e >= E) return;
    atomicAdd(&g_agg1[dst[e]], ew[e] * x[src[e]]);
}

// h1 = relu(agg1 * W1rel + b1 + x * W1root); also count nodes per graph
__global__ void node1_kernel(const float* __restrict__ x, const int* __restrict__ batch,
                             const float* __restrict__ Wrel, const float* __restrict__ b,
                             const float* __restrict__ Wroot, int n) {
    int idx = blockIdx.x * blockDim.x + threadIdx.x;
    if (idx >= n * 16) return;
    int node = idx >> 4, j4 = idx & 15;
    float a = g_agg1[node];
    float xv = x[node];
    float4 wr = __ldg((const float4*)Wrel + j4);
    float4 wo = __ldg((const float4*)Wroot + j4);
    float4 bb = __ldg((const float4*)b + j4);
    float4 h;
    h.x = fmaxf(fmaf(a, wr.x, fmaf(xv, wo.x, bb.x)), 0.f);
    h.y = fmaxf(fmaf(a, wr.y, fmaf(xv, wo.y, bb.y)), 0.f);
    h.z = fmaxf(fmaf(a, wr.z, fmaf(xv, wo.z, bb.z)), 0.f);
    h.w = fmaxf(fmaf(a, wr.w, fmaf(xv, wo.w, bb.w)), 0.f);
    ((float4*)g_h1)[node * 16 + j4] = h;
    if (j4 == 0) atomicAdd(&g_cnt[batch[node]], 1.0f);
}

// ---------------- edge scatter for H=64 layers ----------------
// one thread per (edge, 4-channel chunk); vector no-return atomic add
template <int LAYER>
__global__ void scatterH_kernel(const int* __restrict__ src, const int* __restrict__ dst,
                                const float* __restrict__ ew, int E) {
    int idx = blockIdx.x * blockDim.x + threadIdx.x;
    int e = idx >> 4, c = idx & 15;
    if (e >= E) return;
    const float* hin = (LAYER == 2) ? g_h1 : g_h2;
    float* agg = (LAYER == 2) ? g_aggA : g_aggB;
    int s = __ldg(src + e);
    int d = __ldg(dst + e);
    float w = __ldg(ew + e);
    float4 v = __ldg((const float4*)(hin + s * HD) + c);
    v.x *= w; v.y *= w; v.z *= w; v.w *= w;
    red_add_v4(agg + d * HD + c * 4, v);
}

// ---------------- fused node GEMM: out = agg @ Wrel + b + hin @ Wroot ----------------
// LAYER==2: relu + store to g_h2.   LAYER==3: no relu, pool (red into g_sums), no store.
// Block: 32 nodes, 256 threads. Shared = 32KB weights [128][64] + 16KB X^T [128][32] = 48KB.
template <int LAYER>
__global__ void gemm_kernel(const float* __restrict__ Wrel, const float* __restrict__ Wroot,
                            const float* __restrict__ bias, const int* __restrict__ batch, int n) {
    __shared__ float smem[128 * 64 + 128 * 32];
    float* sW = smem;             // [k:0..127][j:0..63] ; k<64 = Wrel, k>=64 = Wroot
    float* sXT = smem + 128 * 64; // [k:0..127][node:0..31]
    const float* A = (LAYER == 2) ? g_aggA : g_aggB;
    const float* Hin = (LAYER == 2) ? g_h1 : g_h2;
    int tid = threadIdx.x;
    int n0 = blockIdx.x * 32;

    // load weights (1024 float4 each)
    for (int i = tid; i < 1024; i += 256) {
        ((float4*)sW)[i] = __ldg((const float4*)Wrel + i);
        ((float4*)sW)[i + 1024] = __ldg((const float4*)Wroot + i);
    }
    // load X transposed: i -> node = i&31, c4 = i>>5 (0..31); cols 0..15 from A, 16..31 from Hin
    for (int i = tid; i < 1024; i += 256) {
        int node = i & 31, c4 = i >> 5;
        int gn = n0 + node;
        float4 v = make_float4(0.f, 0.f, 0.f, 0.f);
        if (gn < n) {
            v = (c4 < 16) ? __ldg((const float4*)(A + gn * HD) + c4)
                          : __ldg((const float4*)(Hin + gn * HD) + (c4 - 16));
        }
        int kb = c4 * 4;
        sXT[(kb + 0) * 32 + node] = v.x;
        sXT[(kb + 1) * 32 + node] = v.y;
        sXT[(kb + 2) * 32 + node] = v.z;
        sXT[(kb + 3) * 32 + node] = v.w;
    }
    __syncthreads();

    int j4 = tid & 15, nh = tid >> 4; // thread: channels j4*4..+3, nodes nh and nh+16
    float4 acc0 = make_float4(0.f, 0.f, 0.f, 0.f);
    float4 acc1 = make_float4(0.f, 0.f, 0.f, 0.f);
#pragma unroll 8
    for (int k = 0; k < 128; k++) {
        float4 w = *(const float4*)(sW + k * 64 + j4 * 4);
        float a0 = sXT[k * 32 + nh];
        float a1 = sXT[k * 32 + nh + 16];
        acc0.x = fmaf(a0, w.x, acc0.x);
        acc0.y = fmaf(a0, w.y, acc0.y);
        acc0.z = fmaf(a0, w.z, acc0.z);
        acc0.w = fmaf(a0, w.w, acc0.w);
        acc1.x = fmaf(a1, w.x, acc1.x);
        acc1.y = fmaf(a1, w.y, acc1.y);
        acc1.z = fmaf(a1, w.z, acc1.z);
        acc1.w = fmaf(a1, w.w, acc1.w);
    }
    float4 bb = __ldg((const float4*)bias + j4);
    acc0.x += bb.x; acc0.y += bb.y; acc0.z += bb.z; acc0.w += bb.w;
    acc1.x += bb.x; acc1.y += bb.y; acc1.z += bb.z; acc1.w += bb.w;

    int gn0 = n0 + nh, gn1 = gn0 + 16;
    if (LAYER == 2) {
        acc0.x = fmaxf(acc0.x, 0.f); acc0.y = fmaxf(acc0.y, 0.f);
        acc0.z = fmaxf(acc0.z, 0.f); acc0.w = fmaxf(acc0.w, 0.f);
        acc1.x = fmaxf(acc1.x, 0.f); acc1.y = fmaxf(acc1.y, 0.f);
        acc1.z = fmaxf(acc1.z, 0.f); acc1.w = fmaxf(acc1.w, 0.f);
        if (gn0 < n) ((float4*)(g_h2 + gn0 * HD))[j4] = acc0;
        if (gn1 < n) ((float4*)(g_h2 + gn1 * HD))[j4] = acc1;
    } else {
        if (gn0 < n) red_add_v4(g_sums + batch[gn0] * HD + j4 * 4, acc0);
        if (gn1 < n) red_add_v4(g_sums + batch[gn1] * HD + j4 * 4, acc1);
    }
}

// ---------------- head: out[g,c] = dot(sums[g]/cnt[g], Wlin[:,c]) + blin[c] ----------------
__global__ void head_kernel(const float* __restrict__ Wlin, const float* __restrict__ blin,
                            float* __restrict__ out, int g) {
    int idx = blockIdx.x * blockDim.x + threadIdx.x;
    if (idx >= g * 2) return;
    int gi = idx >> 1, c = idx & 1;
    float inv = 1.0f / fmaxf(g_cnt[gi], 1.0f);
    float acc = 0.f;
#pragma unroll
    for (int k = 0; k < HD; k++)
        acc = fmaf(g_sums[gi * HD + k], Wlin[k * 2 + c], acc);
    out[idx] = fmaf(acc, inv, blin[c]);
}

extern "C" void kernel_launch(void* const* d_in, const int* in_sizes, int n_in,
                              void* d_out, int out_size) {
    const float* x      = (const float*)d_in[0];
    const int*   ei     = (const int*)d_in[1];
    const int*   batch  = (const int*)d_in[2];
    const float* ew     = (const float*)d_in[3];
    const float* W1rel  = (const float*)d_in[4];
    const float* b1     = (const float*)d_in[5];
    const float* W1root = (const float*)d_in[6];
    const float* W2rel  = (const float*)d_in[7];
    const float* b2     = (const float*)d_in[8];
    const float* W2root = (const float*)d_in[9];
    const float* W3rel  = (const float*)d_in[10];
    const float* b3     = (const float*)d_in[11];
    const float* W3root = (const float*)d_in[12];
    const float* Wlin   = (const float*)d_in[13];
    const float* blin   = (const float*)d_in[14];

    int N = in_sizes[0];        // x is [N,1]
    int E = in_sizes[3];        // edge_weight is [E]
    int G = out_size / 2;

    const int* src = ei;
    const int* dst = ei + E;
    float* out = (float*)d_out;

    zero_kernel<<<1024, 256>>>(N, G);
    scatter1_kernel<<<(E + 255) / 256, 256>>>(src, dst, ew, x, E);
    node1_kernel<<<(N * 16 + 255) / 256, 256>>>(x, batch, W1rel, b1, W1root, N);
    scatterH_kernel<2><<<(E * 16 + 255) / 256, 256>>>(src, dst, ew, E);
    gemm_kernel<2><<<(N + 31) / 32, 256>>>(W2rel, W2root, b2, batch, N);
    scatterH_kernel<3><<<(E * 16 + 255) / 256, 256>>>(src, dst, ew, E);
    gemm_kernel<3><<<(N + 31) / 32, 256>>>(W3rel, W3root, b3, batch, N);
    head_kernel<<<(G * 2 + 255) / 256, 256>>>(Wlin, blin, out, G);
}

// round 3
// speedup vs baseline: 1.0805x; 1.0805x over previous
#include <cuda_runtime.h>

#define HD 64
#define FULL 0xFFFFFFFFu

static const int N_CAP = 100000;
static const int E_CAP = 1200000;
static const int G_CAP = 256;

// Scratch (allocation-free: __device__ globals; only ever referenced in device code)
__device__ int   g_deg[N_CAP];
__device__ int   g_off[N_CAP];
__device__ int   g_cur[N_CAP];
__device__ int   g_total;
__device__ int   g_csr_src[E_CAP];
__device__ float g_csr_w[E_CAP];
__device__ float g_h1[N_CAP * HD];
__device__ float g_h2[N_CAP * HD];
__device__ float g_agg[N_CAP * HD];
__device__ float g_sums[G_CAP * HD];
__device__ float g_cnt[G_CAP];

__device__ __forceinline__ void red_add_v4(float* p, float4 v) {
    asm volatile("red.global.add.v4.f32 [%0], {%1,%2,%3,%4};"
                 :: "l"(p), "f"(v.x), "f"(v.y), "f"(v.z), "f"(v.w) : "memory");
}

// ---------------- init: zero deg / sums / cnt / total ----------------
__global__ void init_kernel(int n, int g) {
    int i = blockIdx.x * blockDim.x + threadIdx.x;
    int stride = gridDim.x * blockDim.x;
    for (int k = i; k < n; k += stride) g_deg[k] = 0;
    int sv = g * HD;
    for (int k = i; k < sv; k += stride) g_sums[k] = 0.f;
    for (int k = i; k < g; k += stride) g_cnt[k] = 0.f;
    if (i == 0) g_total = 0;
}

// ---------------- CSR build ----------------
__global__ void hist_kernel(const int* __restrict__ dst, int E) {
    int e = blockIdx.x * blockDim.x + threadIdx.x;
    if (e < E) atomicAdd(&g_deg[dst[e]], 1);
}

// segment order in memory is irrelevant -> no scan needed, one atomic cursor
__global__ void offs_kernel(int n) {
    int i = blockIdx.x * blockDim.x + threadIdx.x;
    if (i >= n) return;
    int d = g_deg[i];
    int o = atomicAdd(&g_total, d);
    g_off[i] = o;
    g_cur[i] = o;
}

__global__ void fill_kernel(const int* __restrict__ src, const int* __restrict__ dst,
                            const float* __restrict__ ew, int E) {
    int e = blockIdx.x * blockDim.x + threadIdx.x;
    if (e >= E) return;
    int d = dst[e];
    int p = atomicAdd(&g_cur[d], 1);
    g_csr_src[p] = src[e];
    g_csr_w[p] = ew[e];
}

// ---------------- layer 1 fused: agg (C=1 gather) + node transform + graph counts ----
// warp per node
__global__ void layer1_kernel(const float* __restrict__ x, const int* __restrict__ batch,
                              const float* __restrict__ Wrel, const float* __restrict__ b,
                              const float* __restrict__ Wroot, int n) {
    int gtid = blockIdx.x * blockDim.x + threadIdx.x;
    int node = gtid >> 5, lane = gtid & 31;
    if (node >= n) return;

    int off = g_off[node], deg = g_deg[node], end = off + deg;
    float a = 0.f;
    for (int i = off + lane; i < end; i += 32)
        a = fmaf(__ldg(g_csr_w + i), __ldg(x + __ldg(g_csr_src + i)), a);
#pragma unroll
    for (int s = 16; s > 0; s >>= 1) a += __shfl_xor_sync(FULL, a, s);

    float xv = __ldg(x + node);
    float wr0 = __ldg(Wrel + lane), wr1 = __ldg(Wrel + 32 + lane);
    float wo0 = __ldg(Wroot + lane), wo1 = __ldg(Wroot + 32 + lane);
    float b0 = __ldg(b + lane), b1 = __ldg(b + 32 + lane);
    g_h1[node * HD + lane]      = fmaxf(fmaf(a, wr0, fmaf(xv, wo0, b0)), 0.f);
    g_h1[node * HD + 32 + lane] = fmaxf(fmaf(a, wr1, fmaf(xv, wo1, b1)), 0.f);
    if (lane == 0) atomicAdd(&g_cnt[batch[node]], 1.0f);
}

// ---------------- H-layer aggregation: warp-per-node gather-reduce (no atomics) -----
// LAYER==2: reads g_h1.  LAYER==3: reads g_h2.  Writes g_agg.
template <int LAYER>
__global__ void aggH_kernel(int n) {
    const float* __restrict__ hin = (LAYER == 2) ? g_h1 : g_h2;
    int gtid = blockIdx.x * blockDim.x + threadIdx.x;
    int node = gtid >> 5, lane = gtid & 31;
    if (node >= n) return;

    int off = g_off[node], end = off + g_deg[node];
    float a0 = 0.f, a1 = 0.f;
    for (int base = off; base < end; base += 32) {
        int idx = base + lane;
        int s = 0; float w = 0.f;
        if (idx < end) { s = __ldg(g_csr_src + idx); w = __ldg(g_csr_w + idx); }
        int m = min(32, end - base);
#pragma unroll 4
        for (int j = 0; j < m; j++) {
            int ss = __shfl_sync(FULL, s, j);
            float ww = __shfl_sync(FULL, w, j);
            a0 = fmaf(ww, __ldg(hin + ss * HD + lane), a0);
            a1 = fmaf(ww, __ldg(hin + ss * HD + 32 + lane), a1);
        }
    }
    g_agg[node * HD + lane] = a0;
    g_agg[node * HD + 32 + lane] = a1;
}

// ---------------- fused node GEMM: out = agg @ Wrel + b + hin @ Wroot ----------------
// LAYER==2: relu + store to g_h2.   LAYER==3: no relu, pool (red into g_sums), no store.
template <int LAYER>
__global__ void gemm_kernel(const float* __restrict__ Wrel, const float* __restrict__ Wroot,
                            const float* __restrict__ bias, const int* __restrict__ batch, int n) {
    __shared__ float smem[128 * 64 + 128 * 32];
    float* sW = smem;             // [k:0..127][j:0..63] ; k<64 = Wrel, k>=64 = Wroot
    float* sXT = smem + 128 * 64; // [k:0..127][node:0..31]
    const float* A = g_agg;
    const float* Hin = (LAYER == 2) ? g_h1 : g_h2;
    int tid = threadIdx.x;
    int n0 = blockIdx.x * 32;

    for (int i = tid; i < 1024; i += 256) {
        ((float4*)sW)[i] = __ldg((const float4*)Wrel + i);
        ((float4*)sW)[i + 1024] = __ldg((const float4*)Wroot + i);
    }
    for (int i = tid; i < 1024; i += 256) {
        int node = i & 31, c4 = i >> 5;
        int gn = n0 + node;
        float4 v = make_float4(0.f, 0.f, 0.f, 0.f);
        if (gn < n) {
            v = (c4 < 16) ? __ldg((const float4*)(A + gn * HD) + c4)
                          : __ldg((const float4*)(Hin + gn * HD) + (c4 - 16));
        }
        int kb = c4 * 4;
        sXT[(kb + 0) * 32 + node] = v.x;
        sXT[(kb + 1) * 32 + node] = v.y;
        sXT[(kb + 2) * 32 + node] = v.z;
        sXT[(kb + 3) * 32 + node] = v.w;
    }
    __syncthreads();

    int j4 = tid & 15, nh = tid >> 4;
    float4 acc0 = make_float4(0.f, 0.f, 0.f, 0.f);
    float4 acc1 = make_float4(0.f, 0.f, 0.f, 0.f);
#pragma unroll 8
    for (int k = 0; k < 128; k++) {
        float4 w = *(const float4*)(sW + k * 64 + j4 * 4);
        float a0 = sXT[k * 32 + nh];
        float a1 = sXT[k * 32 + nh + 16];
        acc0.x = fmaf(a0, w.x, acc0.x);
        acc0.y = fmaf(a0, w.y, acc0.y);
        acc0.z = fmaf(a0, w.z, acc0.z);
        acc0.w = fmaf(a0, w.w, acc0.w);
        acc1.x = fmaf(a1, w.x, acc1.x);
        acc1.y = fmaf(a1, w.y, acc1.y);
        acc1.z = fmaf(a1, w.z, acc1.z);
        acc1.w = fmaf(a1, w.w, acc1.w);
    }
    float4 bb = __ldg((const float4*)bias + j4);
    acc0.x += bb.x; acc0.y += bb.y; acc0.z += bb.z; acc0.w += bb.w;
    acc1.x += bb.x; acc1.y += bb.y; acc1.z += bb.z; acc1.w += bb.w;

    int gn0 = n0 + nh, gn1 = gn0 + 16;
    if (LAYER == 2) {
        acc0.x = fmaxf(acc0.x, 0.f); acc0.y = fmaxf(acc0.y, 0.f);
        acc0.z = fmaxf(acc0.z, 0.f); acc0.w = fmaxf(acc0.w, 0.f);
        acc1.x = fmaxf(acc1.x, 0.f); acc1.y = fmaxf(acc1.y, 0.f);
        acc1.z = fmaxf(acc1.z, 0.f); acc1.w = fmaxf(acc1.w, 0.f);
        if (gn0 < n) ((float4*)(g_h2 + gn0 * HD))[j4] = acc0;
        if (gn1 < n) ((float4*)(g_h2 + gn1 * HD))[j4] = acc1;
    } else {
        if (gn0 < n) red_add_v4(g_sums + batch[gn0] * HD + j4 * 4, acc0);
        if (gn1 < n) red_add_v4(g_sums + batch[gn1] * HD + j4 * 4, acc1);
    }
}

// ---------------- head ----------------
__global__ void head_kernel(const float* __restrict__ Wlin, const float* __restrict__ blin,
                            float* __restrict__ out, int g) {
    int idx = blockIdx.x * blockDim.x + threadIdx.x;
    if (idx >= g * 2) return;
    int gi = idx >> 1, c = idx & 1;
    float inv = 1.0f / fmaxf(g_cnt[gi], 1.0f);
    float acc = 0.f;
#pragma unroll
    for (int k = 0; k < HD; k++)
        acc = fmaf(g_sums[gi * HD + k], Wlin[k * 2 + c], acc);
    out[idx] = fmaf(acc, inv, blin[c]);
}

extern "C" void kernel_launch(void* const* d_in, const int* in_sizes, int n_in,
                              void* d_out, int out_size) {
    const float* x      = (const float*)d_in[0];
    const int*   ei     = (const int*)d_in[1];
    const int*   batch  = (const int*)d_in[2];
    const float* ew     = (const float*)d_in[3];
    const float* W1rel  = (const float*)d_in[4];
    const float* b1     = (const float*)d_in[5];
    const float* W1root = (const float*)d_in[6];
    const float* W2rel  = (const float*)d_in[7];
    const float* b2     = (const float*)d_in[8];
    const float* W2root = (const float*)d_in[9];
    const float* W3rel  = (const float*)d_in[10];
    const float* b3     = (const float*)d_in[11];
    const float* W3root = (const float*)d_in[12];
    const float* Wlin   = (const float*)d_in[13];
    const float* blin   = (const float*)d_in[14];

    int N = in_sizes[0];        // x is [N,1]
    int E = in_sizes[3];        // edge_weight is [E]
    int G = out_size / 2;

    const int* src = ei;
    const int* dst = ei + E;
    float* out = (float*)d_out;

    init_kernel<<<256, 256>>>(N, G);
    hist_kernel<<<(E + 255) / 256, 256>>>(dst, E);
    offs_kernel<<<(N + 255) / 256, 256>>>(N);
    fill_kernel<<<(E + 255) / 256, 256>>>(src, dst, ew, E);

    layer1_kernel<<<(N * 32 + 255) / 256, 256>>>(x, batch, W1rel, b1, W1root, N);
    aggH_kernel<2><<<(N * 32 + 255) / 256, 256>>>(N);
    gemm_kernel<2><<<(N + 31) / 32, 256>>>(W2rel, W2root, b2, batch, N);
    aggH_kernel<3><<<(N * 32 + 255) / 256, 256>>>(N);
    gemm_kernel<3><<<(N + 31) / 32, 256>>>(W3rel, W3root, b3, batch, N);
    head_kernel<<<(G * 2 + 255) / 256, 256>>>(Wlin, blin, out, G);
}

// round 4
// speedup vs baseline: 1.2076x; 1.1176x over previous
#include <cuda_runtime.h>

#define HD 64
#define FULL 0xFFFFFFFFu

static const int N_CAP = 100000;
static const int E_CAP = 1200000;
static const int G_CAP = 256;

// Scratch (allocation-free: __device__ globals; only referenced in device code)
__device__ int   g_deg[N_CAP];
__device__ int   g_off[N_CAP];
__device__ int   g_cur[N_CAP];
__device__ int   g_total;
__device__ int2  g_csr[E_CAP];        // {src, w bits}
__device__ float g_h1[N_CAP * HD];
__device__ float g_h2[N_CAP * HD];
__device__ float g_agg[N_CAP * HD];
__device__ float g_sums[G_CAP * HD];
__device__ float g_cnt[G_CAP];

__device__ __forceinline__ void red_add_v4(float* p, float4 v) {
    asm volatile("red.global.add.v4.f32 [%0], {%1,%2,%3,%4};"
                 :: "l"(p), "f"(v.x), "f"(v.y), "f"(v.z), "f"(v.w) : "memory");
}

// ---------------- init: zero deg / sums / cnt / total ----------------
__global__ void init_kernel(int n, int g) {
    int i = blockIdx.x * blockDim.x + threadIdx.x;
    int stride = gridDim.x * blockDim.x;
    for (int k = i; k < n; k += stride) g_deg[k] = 0;
    int sv = g * HD;
    for (int k = i; k < sv; k += stride) g_sums[k] = 0.f;
    for (int k = i; k < g; k += stride) g_cnt[k] = 0.f;
    if (i == 0) g_total = 0;
}

// ---------------- CSR build ----------------
__global__ void hist_kernel(const int* __restrict__ dst, int E) {
    int t = blockIdx.x * blockDim.x + threadIdx.x;
    int i = t * 4;
    if (i + 3 < E) {
        int4 d = __ldg((const int4*)(dst + i));
        atomicAdd(&g_deg[d.x], 1);
        atomicAdd(&g_deg[d.y], 1);
        atomicAdd(&g_deg[d.z], 1);
        atomicAdd(&g_deg[d.w], 1);
    } else {
        for (int e = i; e < E; e++) atomicAdd(&g_deg[dst[e]], 1);
    }
}

// segment order in memory is irrelevant -> no scan needed, one atomic cursor
__global__ void offs_kernel(int n) {
    int i = blockIdx.x * blockDim.x + threadIdx.x;
    if (i >= n) return;
    int d = g_deg[i];
    int o = atomicAdd(&g_total, d);
    g_off[i] = o;
    g_cur[i] = o;
}

__global__ void fill_kernel(const int* __restrict__ src, const int* __restrict__ dst,
                            const float* __restrict__ ew, int E) {
    int e0 = (blockIdx.x * blockDim.x + threadIdx.x) * 2;
    if (e0 >= E) return;
    int d0 = __ldg(dst + e0), s0 = __ldg(src + e0);
    float w0 = __ldg(ew + e0);
    int e1 = e0 + 1;
    int d1 = 0, s1 = 0; float w1 = 0.f;
    bool has1 = e1 < E;
    if (has1) { d1 = __ldg(dst + e1); s1 = __ldg(src + e1); w1 = __ldg(ew + e1); }
    int p0 = atomicAdd(&g_cur[d0], 1);
    g_csr[p0] = make_int2(s0, __float_as_int(w0));
    if (has1) {
        int p1 = atomicAdd(&g_cur[d1], 1);
        g_csr[p1] = make_int2(s1, __float_as_int(w1));
    }
}

// ---------------- layer 1 fused: agg (C=1 gather) + node transform + graph counts ----
// warp per node
__global__ void layer1_kernel(const float* __restrict__ x, const int* __restrict__ batch,
                              const float* __restrict__ Wrel, const float* __restrict__ b,
                              const float* __restrict__ Wroot, int n) {
    int gtid = blockIdx.x * blockDim.x + threadIdx.x;
    int node = gtid >> 5, lane = gtid & 31;
    if (node >= n) return;

    int off = g_off[node], deg = g_deg[node], end = off + deg;
    float a = 0.f;
    for (int i = off + lane; i < end; i += 32) {
        int2 p = __ldg(g_csr + i);
        a = fmaf(__int_as_float(p.y), __ldg(x + p.x), a);
    }
#pragma unroll
    for (int s = 16; s > 0; s >>= 1) a += __shfl_xor_sync(FULL, a, s);

    float xv = __ldg(x + node);
    float wr0 = __ldg(Wrel + lane), wr1 = __ldg(Wrel + 32 + lane);
    float wo0 = __ldg(Wroot + lane), wo1 = __ldg(Wroot + 32 + lane);
    float b0 = __ldg(b + lane), b1 = __ldg(b + 32 + lane);
    g_h1[node * HD + lane]      = fmaxf(fmaf(a, wr0, fmaf(xv, wo0, b0)), 0.f);
    g_h1[node * HD + 32 + lane] = fmaxf(fmaf(a, wr1, fmaf(xv, wo1, b1)), 0.f);
    if (lane == 0) atomicAdd(&g_cnt[batch[node]], 1.0f);
}

// ---------------- H-layer aggregation: warp-per-node gather-reduce (no atomics) -----
// Half-warp per edge: 16 lanes x float4 = one 256B node row. Two edges per step.
template <int LAYER>
__global__ void aggH_kernel(int n) {
    const float* __restrict__ hin = (LAYER == 2) ? g_h1 : g_h2;
    int gtid = blockIdx.x * blockDim.x + threadIdx.x;
    int node = gtid >> 5, lane = gtid & 31;
    if (node >= n) return;

    int off = g_off[node], end = off + g_deg[node];
    int half = lane >> 4, hl = lane & 15;
    float4 acc = make_float4(0.f, 0.f, 0.f, 0.f);

    for (int base = off; base < end; base += 32) {
        int idx = base + lane;
        int2 p = make_int2(0, 0);
        if (idx < end) p = __ldg(g_csr + idx);
        int m = end - base;  // edges in this batch (may exceed 32 only logically; loads capped)
        if (m > 32) m = 32;
#pragma unroll 4
        for (int j = 0; j < 16; j++) {
            if (2 * j >= m) break;              // warp-uniform
            int e = 2 * j + half;
            int ss = __shfl_sync(FULL, p.x, e);
            int wb = __shfl_sync(FULL, p.y, e);
            if (e < m) {
                float ww = __int_as_float(wb);
                float4 v = __ldg((const float4*)(hin + ss * HD) + hl);
                acc.x = fmaf(ww, v.x, acc.x);
                acc.y = fmaf(ww, v.y, acc.y);
                acc.z = fmaf(ww, v.z, acc.z);
                acc.w = fmaf(ww, v.w, acc.w);
            }
        }
    }
    // combine halves (lane l with l^16 hold same channels, different edges)
    acc.x += __shfl_xor_sync(FULL, acc.x, 16);
    acc.y += __shfl_xor_sync(FULL, acc.y, 16);
    acc.z += __shfl_xor_sync(FULL, acc.z, 16);
    acc.w += __shfl_xor_sync(FULL, acc.w, 16);
    if (half == 0) ((float4*)(g_agg + node * HD))[hl] = acc;
}

// ---------------- fused node GEMM: out = agg @ Wrel + b + hin @ Wroot ----------------
// 128-node tile, 128 threads, 8x8 register tile, two K=64 passes sharing accumulators.
// LAYER==2: relu + store to g_h2.   LAYER==3: no relu, pool (red into g_sums).
template <int LAYER>
__global__ void __launch_bounds__(128, 4) gemm_kernel(
        const float* __restrict__ Wrel, const float* __restrict__ Wroot,
        const float* __restrict__ bias, const int* __restrict__ batch, int n) {
    __shared__ float sW[64 * 64];    // [k][j]
    __shared__ float sXT[64 * 128];  // [k][node]
    const float* Hin = (LAYER == 2) ? g_h1 : g_h2;
    int tid = threadIdx.x;
    int cg = tid & 7;        // channel group: channels cg*8 .. cg*8+7
    int ng = tid >> 3;       // node group:    nodes ng*8 .. ng*8+7
    int n0 = blockIdx.x * 128;

    float4 accA[8], accB[8];
#pragma unroll
    for (int r = 0; r < 8; r++) {
        accA[r] = make_float4(0.f, 0.f, 0.f, 0.f);
        accB[r] = make_float4(0.f, 0.f, 0.f, 0.f);
    }

#pragma unroll
    for (int pass = 0; pass < 2; pass++) {
        const float* Xsrc = pass ? Hin : g_agg;
        const float* W = pass ? Wroot : Wrel;
        for (int i = tid; i < 1024; i += 128)
            ((float4*)sW)[i] = __ldg((const float4*)W + i);
        for (int i = tid; i < 2048; i += 128) {
            int node = i & 127, c4 = i >> 7;
            int gn = n0 + node;
            float4 v = make_float4(0.f, 0.f, 0.f, 0.f);
            if (gn < n) v = __ldg((const float4*)(Xsrc + gn * HD) + c4);
            int k = c4 * 4;
            sXT[(k + 0) * 128 + node] = v.x;
            sXT[(k + 1) * 128 + node] = v.y;
            sXT[(k + 2) * 128 + node] = v.z;
            sXT[(k + 3) * 128 + node] = v.w;
        }
        __syncthreads();

#pragma unroll 8
        for (int k = 0; k < 64; k++) {
            float4 w0 = *(const float4*)(sW + k * 64 + cg * 8);
            float4 w1 = *(const float4*)(sW + k * 64 + cg * 8 + 4);
            float4 x0 = *(const float4*)(sXT + k * 128 + ng * 8);
            float4 x1 = *(const float4*)(sXT + k * 128 + ng * 8 + 4);
            float xs[8] = {x0.x, x0.y, x0.z, x0.w, x1.x, x1.y, x1.z, x1.w};
#pragma unroll
            for (int r = 0; r < 8; r++) {
                accA[r].x = fmaf(xs[r], w0.x, accA[r].x);
                accA[r].y = fmaf(xs[r], w0.y, accA[r].y);
                accA[r].z = fmaf(xs[r], w0.z, accA[r].z);
                accA[r].w = fmaf(xs[r], w0.w, accA[r].w);
                accB[r].x = fmaf(xs[r], w1.x, accB[r].x);
                accB[r].y = fmaf(xs[r], w1.y, accB[r].y);
                accB[r].z = fmaf(xs[r], w1.z, accB[r].z);
                accB[r].w = fmaf(xs[r], w1.w, accB[r].w);
            }
        }
        __syncthreads();
    }

    float4 bb0 = __ldg((const float4*)bias + cg * 2);
    float4 bb1 = __ldg((const float4*)bias + cg * 2 + 1);
#pragma unroll
    for (int r = 0; r < 8; r++) {
        int gn = n0 + ng * 8 + r;
        if (gn >= n) break;
        float4 oa = accA[r], ob = accB[r];
        oa.x += bb0.x; oa.y += bb0.y; oa.z += bb0.z; oa.w += bb0.w;
        ob.x += bb1.x; ob.y += bb1.y; ob.z += bb1.z; ob.w += bb1.w;
        if (LAYER == 2) {
            oa.x = fmaxf(oa.x, 0.f); oa.y = fmaxf(oa.y, 0.f);
            oa.z = fmaxf(oa.z, 0.f); oa.w = fmaxf(oa.w, 0.f);
            ob.x = fmaxf(ob.x, 0.f); ob.y = fmaxf(ob.y, 0.f);
            ob.z = fmaxf(ob.z, 0.f); ob.w = fmaxf(ob.w, 0.f);
            float4* dst4 = (float4*)(g_h2 + gn * HD + cg * 8);
            dst4[0] = oa;
            dst4[1] = ob;
        } else {
            float* sp = g_sums + batch[gn] * HD + cg * 8;
            red_add_v4(sp, oa);
            red_add_v4(sp + 4, ob);
        }
    }
}

// ---------------- head ----------------
__global__ void head_kernel(const float* __restrict__ Wlin, const float* __restrict__ blin,
                            float* __restrict__ out, int g) {
    int idx = blockIdx.x * blockDim.x + threadIdx.x;
    if (idx >= g * 2) return;
    int gi = idx >> 1, c = idx & 1;
    float inv = 1.0f / fmaxf(g_cnt[gi], 1.0f);
    float acc = 0.f;
#pragma unroll
    for (int k = 0; k < HD; k++)
        acc = fmaf(g_sums[gi * HD + k], Wlin[k * 2 + c], acc);
    out[idx] = fmaf(acc, inv, blin[c]);
}

extern "C" void kernel_launch(void* const* d_in, const int* in_sizes, int n_in,
                              void* d_out, int out_size) {
    const float* x      = (const float*)d_in[0];
    const int*   ei     = (const int*)d_in[1];
    const int*   batch  = (const int*)d_in[2];
    const float* ew     = (const float*)d_in[3];
    const float* W1rel  = (const float*)d_in[4];
    const float* b1     = (const float*)d_in[5];
    const float* W1root = (const float*)d_in[6];
    const float* W2rel  = (const float*)d_in[7];
    const float* b2     = (const float*)d_in[8];
    const float* W2root = (const float*)d_in[9];
    const float* W3rel  = (const float*)d_in[10];
    const float* b3     = (const float*)d_in[11];
    const float* W3root = (const float*)d_in[12];
    const float* Wlin   = (const float*)d_in[13];
    const float* blin   = (const float*)d_in[14];

    int N = in_sizes[0];        // x is [N,1]
    int E = in_sizes[3];        // edge_weight is [E]
    int G = out_size / 2;

    const int* src = ei;
    const int* dst = ei + E;
    float* out = (float*)d_out;

    init_kernel<<<256, 256>>>(N, G);
    hist_kernel<<<(E / 4 + 256) / 256, 256>>>(dst, E);
    offs_kernel<<<(N + 255) / 256, 256>>>(N);
    fill_kernel<<<(E / 2 + 256) / 256, 256>>>(src, dst, ew, E);

    layer1_kernel<<<(N * 32 + 255) / 256, 256>>>(x, batch, W1rel, b1, W1root, N);
    aggH_kernel<2><<<(N * 32 + 255) / 256, 256>>>(N);
    gemm_kernel<2><<<(N + 127) / 128, 128>>>(W2rel, W2root, b2, batch, N);
    aggH_kernel<3><<<(N * 32 + 255) / 256, 256>>>(N);
    gemm_kernel<3><<<(N + 127) / 128, 128>>>(W3rel, W3root, b3, batch, N);
    head_kernel<<<(G * 2 + 255) / 256, 256>>>(Wlin, blin, out, G);
}

// round 5
// speedup vs baseline: 1.2884x; 1.0670x over previous
#include <cuda_runtime.h>
#include <cuda_fp16.h>

#define HD 64
#define FULL 0xFFFFFFFFu

static const int N_CAP = 100000;
static const int E_CAP = 1200000;
static const int G_CAP = 256;

// Scratch (allocation-free: __device__ globals; only referenced in device code)
__device__ int    g_deg[N_CAP];
__device__ int    g_off[N_CAP];
__device__ int    g_cur[N_CAP];
__device__ int    g_total;
__device__ int2   g_csr[E_CAP];          // {src, w bits}
__device__ __half g_h1[N_CAP * HD];      // fp16 node features (layer1 out)
__device__ __half g_h2[N_CAP * HD];      // fp16 node features (layer2 out)
__device__ float  g_agg[N_CAP * HD];     // fp32 aggregation result
__device__ float  g_sums[G_CAP * HD];
__device__ float  g_cnt[G_CAP];

__device__ __forceinline__ void red_add_v4(float* p, float4 v) {
    asm volatile("red.global.add.v4.f32 [%0], {%1,%2,%3,%4};"
                 :: "l"(p), "f"(v.x), "f"(v.y), "f"(v.z), "f"(v.w) : "memory");
}

// ---------------- init: zero deg / sums / cnt / total ----------------
__global__ void init_kernel(int n, int g) {
    int i = blockIdx.x * blockDim.x + threadIdx.x;
    int stride = gridDim.x * blockDim.x;
    for (int k = i; k < n; k += stride) g_deg[k] = 0;
    int sv = g * HD;
    for (int k = i; k < sv; k += stride) g_sums[k] = 0.f;
    for (int k = i; k < g; k += stride) g_cnt[k] = 0.f;
    if (i == 0) g_total = 0;
}

// ---------------- CSR build ----------------
__global__ void hist_kernel(const int* __restrict__ dst, int E) {
    int t = blockIdx.x * blockDim.x + threadIdx.x;
    int i = t * 4;
    if (i + 3 < E) {
        int4 d = __ldg((const int4*)(dst + i));
        atomicAdd(&g_deg[d.x], 1);
        atomicAdd(&g_deg[d.y], 1);
        atomicAdd(&g_deg[d.z], 1);
        atomicAdd(&g_deg[d.w], 1);
    } else {
        for (int e = i; e < E; e++) atomicAdd(&g_deg[dst[e]], 1);
    }
}

// segment order in memory is irrelevant -> no scan needed, one atomic cursor
__global__ void offs_kernel(int n) {
    int i = blockIdx.x * blockDim.x + threadIdx.x;
    if (i >= n) return;
    int d = g_deg[i];
    int o = atomicAdd(&g_total, d);
    g_off[i] = o;
    g_cur[i] = o;
}

__global__ void fill_kernel(const int* __restrict__ src, const int* __restrict__ dst,
                            const float* __restrict__ ew, int E) {
    int i = (blockIdx.x * blockDim.x + threadIdx.x) * 4;
    if (i + 3 < E) {
        int4 d = __ldg((const int4*)(dst + i));
        int4 s = __ldg((const int4*)(src + i));
        float4 w = __ldg((const float4*)(ew + i));
        int p0 = atomicAdd(&g_cur[d.x], 1);
        int p1 = atomicAdd(&g_cur[d.y], 1);
        int p2 = atomicAdd(&g_cur[d.z], 1);
        int p3 = atomicAdd(&g_cur[d.w], 1);
        g_csr[p0] = make_int2(s.x, __float_as_int(w.x));
        g_csr[p1] = make_int2(s.y, __float_as_int(w.y));
        g_csr[p2] = make_int2(s.z, __float_as_int(w.z));
        g_csr[p3] = make_int2(s.w, __float_as_int(w.w));
    } else {
        for (int e = i; e < E; e++) {
            int p = atomicAdd(&g_cur[__ldg(dst + e)], 1);
            g_csr[p] = make_int2(__ldg(src + e), __float_as_int(__ldg(ew + e)));
        }
    }
}

// ---------------- layer 1 fused: agg (C=1 gather) + node transform + graph counts ----
// warp per node; h1 stored fp16
__global__ void layer1_kernel(const float* __restrict__ x, const int* __restrict__ batch,
                              const float* __restrict__ Wrel, const float* __restrict__ b,
                              const float* __restrict__ Wroot, int n) {
    int gtid = blockIdx.x * blockDim.x + threadIdx.x;
    int node = gtid >> 5, lane = gtid & 31;
    if (node >= n) return;

    int off = g_off[node], deg = g_deg[node], end = off + deg;
    float a = 0.f;
    for (int i = off + lane; i < end; i += 32) {
        int2 p = __ldg(g_csr + i);
        a = fmaf(__int_as_float(p.y), __ldg(x + p.x), a);
    }
#pragma unroll
    for (int s = 16; s > 0; s >>= 1) a += __shfl_xor_sync(FULL, a, s);

    float xv = __ldg(x + node);
    float wr0 = __ldg(Wrel + lane), wr1 = __ldg(Wrel + 32 + lane);
    float wo0 = __ldg(Wroot + lane), wo1 = __ldg(Wroot + 32 + lane);
    float b0 = __ldg(b + lane), b1 = __ldg(b + 32 + lane);
    float h0 = fmaxf(fmaf(a, wr0, fmaf(xv, wo0, b0)), 0.f);
    float h1 = fmaxf(fmaf(a, wr1, fmaf(xv, wo1, b1)), 0.f);
    g_h1[node * HD + lane]      = __float2half_rn(h0);
    g_h1[node * HD + 32 + lane] = __float2half_rn(h1);
    if (lane == 0) atomicAdd(&g_cnt[batch[node]], 1.0f);
}

// ---------------- H-layer aggregation: warp-per-node gather-reduce (no atomics) -----
// fp16 rows: 128B = 16 lanes x 8B (4 halves). Half-warp per edge, 2 edges per step.
template <int LAYER>
__global__ void aggH_kernel(int n) {
    const __half* __restrict__ hin = (LAYER == 2) ? g_h1 : g_h2;
    int gtid = blockIdx.x * blockDim.x + threadIdx.x;
    int node = gtid >> 5, lane = gtid & 31;
    if (node >= n) return;

    int off = g_off[node], end = off + g_deg[node];
    int half = lane >> 4, hl = lane & 15;
    float4 acc = make_float4(0.f, 0.f, 0.f, 0.f);

    for (int base = off; base < end; base += 32) {
        int idx = base + lane;
        int2 p = make_int2(0, 0);
        if (idx < end) p = __ldg(g_csr + idx);
        int m = end - base;
        if (m > 32) m = 32;
#pragma unroll 4
        for (int j = 0; j < 16; j++) {
            if (2 * j >= m) break;              // warp-uniform
            int e = 2 * j + half;
            int ss = __shfl_sync(FULL, p.x, e);
            int wb = __shfl_sync(FULL, p.y, e);
            if (e < m) {
                float ww = __int_as_float(wb);
                int2 raw = __ldg((const int2*)(hin + ss * HD) + hl);  // 4 halves
                __half2 p0 = *(__half2*)&raw.x;
                __half2 p1 = *(__half2*)&raw.y;
                float2 f0 = __half22float2(p0);
                float2 f1 = __half22float2(p1);
                acc.x = fmaf(ww, f0.x, acc.x);
                acc.y = fmaf(ww, f0.y, acc.y);
                acc.z = fmaf(ww, f1.x, acc.z);
                acc.w = fmaf(ww, f1.y, acc.w);
            }
        }
    }
    acc.x += __shfl_xor_sync(FULL, acc.x, 16);
    acc.y += __shfl_xor_sync(FULL, acc.y, 16);
    acc.z += __shfl_xor_sync(FULL, acc.z, 16);
    acc.w += __shfl_xor_sync(FULL, acc.w, 16);
    if (half == 0) ((float4*)(g_agg + node * HD))[hl] = acc;
}

// ---------------- fused node GEMM: out = agg @ Wrel + b + hin @ Wroot ----------------
// 128-node tile, 128 threads, 8x8 register tile, two K=64 passes sharing accumulators.
// pass0: X = g_agg (fp32). pass1: X = hin (fp16 -> fp32 on smem stage).
// LAYER==2: relu + store fp16 to g_h2.   LAYER==3: no relu, pool (red into g_sums).
template <int LAYER>
__global__ void __launch_bounds__(128, 4) gemm_kernel(
        const float* __restrict__ Wrel, const float* __restrict__ Wroot,
        const float* __restrict__ bias, const int* __restrict__ batch, int n) {
    __shared__ float sW[64 * 64];    // [k][j]
    __shared__ float sXT[64 * 128];  // [k][node]
    const __half* Hin = (LAYER == 2) ? g_h1 : g_h2;
    int tid = threadIdx.x;
    int cg = tid & 7;        // channels cg*8 .. cg*8+7
    int ng = tid >> 3;       // nodes ng*8 .. ng*8+7
    int n0 = blockIdx.x * 128;

    float4 accA[8], accB[8];
#pragma unroll
    for (int r = 0; r < 8; r++) {
        accA[r] = make_float4(0.f, 0.f, 0.f, 0.f);
        accB[r] = make_float4(0.f, 0.f, 0.f, 0.f);
    }

#pragma unroll
    for (int pass = 0; pass < 2; pass++) {
        const float* W = pass ? Wroot : Wrel;
        for (int i = tid; i < 1024; i += 128)
            ((float4*)sW)[i] = __ldg((const float4*)W + i);
        for (int i = tid; i < 2048; i += 128) {
            int node = i & 127, c4 = i >> 7;
            int gn = n0 + node;
            float4 v = make_float4(0.f, 0.f, 0.f, 0.f);
            if (gn < n) {
                if (pass == 0) {
                    v = __ldg((const float4*)(g_agg + gn * HD) + c4);
                } else {
                    int2 raw = __ldg((const int2*)(Hin + gn * HD) + c4);
                    float2 f0 = __half22float2(*(__half2*)&raw.x);
                    float2 f1 = __half22float2(*(__half2*)&raw.y);
                    v = make_float4(f0.x, f0.y, f1.x, f1.y);
                }
            }
            int k = c4 * 4;
            sXT[(k + 0) * 128 + node] = v.x;
            sXT[(k + 1) * 128 + node] = v.y;
            sXT[(k + 2) * 128 + node] = v.z;
            sXT[(k + 3) * 128 + node] = v.w;
        }
        __syncthreads();

#pragma unroll 8
        for (int k = 0; k < 64; k++) {
            float4 w0 = *(const float4*)(sW + k * 64 + cg * 8);
            float4 w1 = *(const float4*)(sW + k * 64 + cg * 8 + 4);
            float4 x0 = *(const float4*)(sXT + k * 128 + ng * 8);
            float4 x1 = *(const float4*)(sXT + k * 128 + ng * 8 + 4);
            float xs[8] = {x0.x, x0.y, x0.z, x0.w, x1.x, x1.y, x1.z, x1.w};
#pragma unroll
            for (int r = 0; r < 8; r++) {
                accA[r].x = fmaf(xs[r], w0.x, accA[r].x);
                accA[r].y = fmaf(xs[r], w0.y, accA[r].y);
                accA[r].z = fmaf(xs[r], w0.z, accA[r].z);
                accA[r].w = fmaf(xs[r], w0.w, accA[r].w);
                accB[r].x = fmaf(xs[r], w1.x, accB[r].x);
                accB[r].y = fmaf(xs[r], w1.y, accB[r].y);
                accB[r].z = fmaf(xs[r], w1.z, accB[r].z);
                accB[r].w = fmaf(xs[r], w1.w, accB[r].w);
            }
        }
        __syncthreads();
    }

    float4 bb0 = __ldg((const float4*)bias + cg * 2);
    float4 bb1 = __ldg((const float4*)bias + cg * 2 + 1);
#pragma unroll
    for (int r = 0; r < 8; r++) {
        int gn = n0 + ng * 8 + r;
        if (gn >= n) break;
        float4 oa = accA[r], ob = accB[r];
        oa.x += bb0.x; oa.y += bb0.y; oa.z += bb0.z; oa.w += bb0.w;
        ob.x += bb1.x; ob.y += bb1.y; ob.z += bb1.z; ob.w += bb1.w;
        if (LAYER == 2) {
            oa.x = fmaxf(oa.x, 0.f); oa.y = fmaxf(oa.y, 0.f);
            oa.z = fmaxf(oa.z, 0.f); oa.w = fmaxf(oa.w, 0.f);
            ob.x = fmaxf(ob.x, 0.f); ob.y = fmaxf(ob.y, 0.f);
            ob.z = fmaxf(ob.z, 0.f); ob.w = fmaxf(ob.w, 0.f);
            __half2 h01 = __floats2half2_rn(oa.x, oa.y);
            __half2 h23 = __floats2half2_rn(oa.z, oa.w);
            __half2 h45 = __floats2half2_rn(ob.x, ob.y);
            __half2 h67 = __floats2half2_rn(ob.z, ob.w);
            int4 packed = make_int4(*(int*)&h01, *(int*)&h23, *(int*)&h45, *(int*)&h67);
            *(int4*)(g_h2 + gn * HD + cg * 8) = packed;
        } else {
            float* sp = g_sums + batch[gn] * HD + cg * 8;
            red_add_v4(sp, oa);
            red_add_v4(sp + 4, ob);
        }
    }
}

// ---------------- head ----------------
__global__ void head_kernel(const float* __restrict__ Wlin, const float* __restrict__ blin,
                            float* __restrict__ out, int g) {
    int idx = blockIdx.x * blockDim.x + threadIdx.x;
    if (idx >= g * 2) return;
    int gi = idx >> 1, c = idx & 1;
    float inv = 1.0f / fmaxf(g_cnt[gi], 1.0f);
    float acc = 0.f;
#pragma unroll
    for (int k = 0; k < HD; k++)
        acc = fmaf(g_sums[gi * HD + k], Wlin[k * 2 + c], acc);
    out[idx] = fmaf(acc, inv, blin[c]);
}

extern "C" void kernel_launch(void* const* d_in, const int* in_sizes, int n_in,
                              void* d_out, int out_size) {
    const float* x      = (const float*)d_in[0];
    const int*   ei     = (const int*)d_in[1];
    const int*   batch  = (const int*)d_in[2];
    const float* ew     = (const float*)d_in[3];
    const float* W1rel  = (const float*)d_in[4];
    const float* b1     = (const float*)d_in[5];
    const float* W1root = (const float*)d_in[6];
    const float* W2rel  = (const float*)d_in[7];
    const float* b2     = (const float*)d_in[8];
    const float* W2root = (const float*)d_in[9];
    const float* W3rel  = (const float*)d_in[10];
    const float* b3     = (const float*)d_in[11];
    const float* W3root = (const float*)d_in[12];
    const float* Wlin   = (const float*)d_in[13];
    const float* blin   = (const float*)d_in[14];

    int N = in_sizes[0];        // x is [N,1]
    int E = in_sizes[3];        // edge_weight is [E]
    int G = out_size / 2;

    const int* src = ei;
    const int* dst = ei + E;
    float* out = (float*)d_out;

    init_kernel<<<256, 256>>>(N, G);
    hist_kernel<<<(E / 4 + 256) / 256, 256>>>(dst, E);
    offs_kernel<<<(N + 255) / 256, 256>>>(N);
    fill_kernel<<<(E / 4 + 256) / 256, 256>>>(src, dst, ew, E);

    layer1_kernel<<<(N * 32 + 255) / 256, 256>>>(x, batch, W1rel, b1, W1root, N);
    aggH_kernel<2><<<(N * 32 + 255) / 256, 256>>>(N);
    gemm_kernel<2><<<(N + 127) / 128, 128>>>(W2rel, W2root, b2, batch, N);
    aggH_kernel<3><<<(N * 32 + 255) / 256, 256>>>(N);
    gemm_kernel<3><<<(N + 127) / 128, 128>>>(W3rel, W3root, b3, batch, N);
    head_kernel<<<(G * 2 + 255) / 256, 256>>>(Wlin, blin, out, G);
}

// round 6
// speedup vs baseline: 1.3208x; 1.0251x over previous
#include <cuda_runtime.h>
#include <cuda_fp16.h>

#define HD 64
#define FULL 0xFFFFFFFFu

static const int N_CAP = 100000;
static const int E_CAP = 1200000;
static const int G_CAP = 256;

// Scratch (allocation-free: __device__ globals; only referenced in device code)
__device__ int    g_deg[N_CAP];
__device__ int    g_off[N_CAP];
__device__ int    g_cur[N_CAP];
__device__ int    g_total;
__device__ int2   g_csr[E_CAP];          // {src, w bits}
__device__ __half g_h1[N_CAP * HD];      // fp16 node features (layer1 out)
__device__ __half g_h2[N_CAP * HD];      // fp16 node features (layer2 out)
__device__ float  g_agg[N_CAP * HD];     // fp32 aggregation result
__device__ float  g_sums[G_CAP * HD];
__device__ float  g_cnt[G_CAP];

__device__ __forceinline__ void red_add_v4(float* p, float4 v) {
    asm volatile("red.global.add.v4.f32 [%0], {%1,%2,%3,%4};"
                 :: "l"(p), "f"(v.x), "f"(v.y), "f"(v.z), "f"(v.w) : "memory");
}

// ---------------- init: zero deg / sums / cnt / total ----------------
__global__ void init_kernel(int n, int g) {
    int i = blockIdx.x * blockDim.x + threadIdx.x;
    int stride = gridDim.x * blockDim.x;
    for (int k = i; k < n; k += stride) g_deg[k] = 0;
    int sv = g * HD;
    for (int k = i; k < sv; k += stride) g_sums[k] = 0.f;
    for (int k = i; k < g; k += stride) g_cnt[k] = 0.f;
    if (i == 0) g_total = 0;
}

// ---------------- CSR build ----------------
__global__ void hist_kernel(const int* __restrict__ dst, int E) {
    int t = blockIdx.x * blockDim.x + threadIdx.x;
    int i = t * 4;
    if (i + 3 < E) {
        int4 d = __ldg((const int4*)(dst + i));
        atomicAdd(&g_deg[d.x], 1);
        atomicAdd(&g_deg[d.y], 1);
        atomicAdd(&g_deg[d.z], 1);
        atomicAdd(&g_deg[d.w], 1);
    } else {
        for (int e = i; e < E; e++) atomicAdd(&g_deg[dst[e]], 1);
    }
}

// segment order in memory is irrelevant -> no scan needed, one atomic cursor
__global__ void offs_kernel(int n) {
    int i = blockIdx.x * blockDim.x + threadIdx.x;
    if (i >= n) return;
    int d = g_deg[i];
    int o = atomicAdd(&g_total, d);
    g_off[i] = o;
    g_cur[i] = o;
}

__global__ void fill_kernel(const int* __restrict__ src, const int* __restrict__ dst,
                            const float* __restrict__ ew, int E) {
    int i = (blockIdx.x * blockDim.x + threadIdx.x) * 8;
    if (i + 7 < E) {
        int4 d0 = __ldg((const int4*)(dst + i));
        int4 d1 = __ldg((const int4*)(dst + i + 4));
        int4 s0 = __ldg((const int4*)(src + i));
        int4 s1 = __ldg((const int4*)(src + i + 4));
        float4 w0 = __ldg((const float4*)(ew + i));
        float4 w1 = __ldg((const float4*)(ew + i + 4));
        int p0 = atomicAdd(&g_cur[d0.x], 1);
        int p1 = atomicAdd(&g_cur[d0.y], 1);
        int p2 = atomicAdd(&g_cur[d0.z], 1);
        int p3 = atomicAdd(&g_cur[d0.w], 1);
        int p4 = atomicAdd(&g_cur[d1.x], 1);
        int p5 = atomicAdd(&g_cur[d1.y], 1);
        int p6 = atomicAdd(&g_cur[d1.z], 1);
        int p7 = atomicAdd(&g_cur[d1.w], 1);
        g_csr[p0] = make_int2(s0.x, __float_as_int(w0.x));
        g_csr[p1] = make_int2(s0.y, __float_as_int(w0.y));
        g_csr[p2] = make_int2(s0.z, __float_as_int(w0.z));
        g_csr[p3] = make_int2(s0.w, __float_as_int(w0.w));
        g_csr[p4] = make_int2(s1.x, __float_as_int(w1.x));
        g_csr[p5] = make_int2(s1.y, __float_as_int(w1.y));
        g_csr[p6] = make_int2(s1.z, __float_as_int(w1.z));
        g_csr[p7] = make_int2(s1.w, __float_as_int(w1.w));
    } else {
        for (int e = i; e < E; e++) {
            int p = atomicAdd(&g_cur[__ldg(dst + e)], 1);
            g_csr[p] = make_int2(__ldg(src + e), __float_as_int(__ldg(ew + e)));
        }
    }
}

// ---------------- layer 1 fused: agg (C=1 gather) + node transform + graph counts ----
// warp per node; h1 stored fp16
__global__ void layer1_kernel(const float* __restrict__ x, const int* __restrict__ batch,
                              const float* __restrict__ Wrel, const float* __restrict__ b,
                              const float* __restrict__ Wroot, int n) {
    int gtid = blockIdx.x * blockDim.x + threadIdx.x;
    int node = gtid >> 5, lane = gtid & 31;
    if (node >= n) return;

    int off = g_off[node], deg = g_deg[node], end = off + deg;
    float a = 0.f;
    for (int i = off + lane; i < end; i += 32) {
        int2 p = __ldg(g_csr + i);
        a = fmaf(__int_as_float(p.y), __ldg(x + p.x), a);
    }
#pragma unroll
    for (int s = 16; s > 0; s >>= 1) a += __shfl_xor_sync(FULL, a, s);

    float xv = __ldg(x + node);
    float wr0 = __ldg(Wrel + lane), wr1 = __ldg(Wrel + 32 + lane);
    float wo0 = __ldg(Wroot + lane), wo1 = __ldg(Wroot + 32 + lane);
    float b0 = __ldg(b + lane), b1 = __ldg(b + 32 + lane);
    float h0 = fmaxf(fmaf(a, wr0, fmaf(xv, wo0, b0)), 0.f);
    float h1 = fmaxf(fmaf(a, wr1, fmaf(xv, wo1, b1)), 0.f);
    g_h1[node * HD + lane]      = __float2half_rn(h0);
    g_h1[node * HD + 32 + lane] = __float2half_rn(h1);
    if (lane == 0) atomicAdd(&g_cnt[batch[node]], 1.0f);
}

// ---------------- H-layer aggregation: warp-per-node, lane = channel pair ----------
// Per edge: one warp-uniform CSR load (broadcast) + one half2 gather per lane.
template <int LAYER>
__global__ void aggH_kernel(int n) {
    const __half* __restrict__ hin = (LAYER == 2) ? g_h1 : g_h2;
    int gtid = blockIdx.x * blockDim.x + threadIdx.x;
    int node = gtid >> 5, lane = gtid & 31;
    if (node >= n) return;

    int off = g_off[node], end = off + g_deg[node];
    float a0 = 0.f, a1 = 0.f;

    int i = off;
#pragma unroll 1
    for (; i + 4 <= end; i += 4) {
        int2 p0 = __ldg(g_csr + i);
        int2 p1 = __ldg(g_csr + i + 1);
        int2 p2 = __ldg(g_csr + i + 2);
        int2 p3 = __ldg(g_csr + i + 3);
        __half2 v0 = __ldg((const __half2*)(hin + p0.x * HD) + lane);
        __half2 v1 = __ldg((const __half2*)(hin + p1.x * HD) + lane);
        __half2 v2 = __ldg((const __half2*)(hin + p2.x * HD) + lane);
        __half2 v3 = __ldg((const __half2*)(hin + p3.x * HD) + lane);
        float2 f0 = __half22float2(v0);
        float2 f1 = __half22float2(v1);
        float2 f2 = __half22float2(v2);
        float2 f3 = __half22float2(v3);
        float w0 = __int_as_float(p0.y), w1 = __int_as_float(p1.y);
        float w2 = __int_as_float(p2.y), w3 = __int_as_float(p3.y);
        a0 = fmaf(w0, f0.x, a0); a1 = fmaf(w0, f0.y, a1);
        a0 = fmaf(w1, f1.x, a0); a1 = fmaf(w1, f1.y, a1);
        a0 = fmaf(w2, f2.x, a0); a1 = fmaf(w2, f2.y, a1);
        a0 = fmaf(w3, f3.x, a0); a1 = fmaf(w3, f3.y, a1);
    }
    for (; i < end; i++) {
        int2 p = __ldg(g_csr + i);
        __half2 v = __ldg((const __half2*)(hin + p.x * HD) + lane);
        float2 f = __half22float2(v);
        float w = __int_as_float(p.y);
        a0 = fmaf(w, f.x, a0); a1 = fmaf(w, f.y, a1);
    }
    ((float2*)(g_agg + node * HD))[lane] = make_float2(a0, a1);
}

// ---------------- fused node GEMM: out = agg @ Wrel + b + hin @ Wroot ----------------
// 128-node tile, 128 threads, 8x8 register tile, two K=64 passes sharing accumulators.
// pass0: X = g_agg (fp32). pass1: X = hin (fp16 -> fp32 on smem stage).
// LAYER==2: relu + store fp16 to g_h2.   LAYER==3: no relu, pool (red into g_sums).
template <int LAYER>
__global__ void __launch_bounds__(128, 4) gemm_kernel(
        const float* __restrict__ Wrel, const float* __restrict__ Wroot,
        const float* __restrict__ bias, const int* __restrict__ batch, int n) {
    __shared__ float sW[64 * 64];    // [k][j]
    __shared__ float sXT[64 * 128];  // [k][node]
    const __half* Hin = (LAYER == 2) ? g_h1 : g_h2;
    int tid = threadIdx.x;
    int cg = tid & 7;        // channels cg*8 .. cg*8+7
    int ng = tid >> 3;       // nodes ng*8 .. ng*8+7
    int n0 = blockIdx.x * 128;

    float4 accA[8], accB[8];
#pragma unroll
    for (int r = 0; r < 8; r++) {
        accA[r] = make_float4(0.f, 0.f, 0.f, 0.f);
        accB[r] = make_float4(0.f, 0.f, 0.f, 0.f);
    }

#pragma unroll
    for (int pass = 0; pass < 2; pass++) {
        const float* W = pass ? Wroot : Wrel;
        for (int i = tid; i < 1024; i += 128)
            ((float4*)sW)[i] = __ldg((const float4*)W + i);
        for (int i = tid; i < 2048; i += 128) {
            int node = i & 127, c4 = i >> 7;
            int gn = n0 + node;
            float4 v = make_float4(0.f, 0.f, 0.f, 0.f);
            if (gn < n) {
                if (pass == 0) {
                    v = __ldg((const float4*)(g_agg + gn * HD) + c4);
                } else {
                    int2 raw = __ldg((const int2*)(Hin + gn * HD) + c4);
                    float2 f0 = __half22float2(*(__half2*)&raw.x);
                    float2 f1 = __half22float2(*(__half2*)&raw.y);
                    v = make_float4(f0.x, f0.y, f1.x, f1.y);
                }
            }
            int k = c4 * 4;
            sXT[(k + 0) * 128 + node] = v.x;
            sXT[(k + 1) * 128 + node] = v.y;
            sXT[(k + 2) * 128 + node] = v.z;
            sXT[(k + 3) * 128 + node] = v.w;
        }
        __syncthreads();

#pragma unroll 8
        for (int k = 0; k < 64; k++) {
            float4 w0 = *(const float4*)(sW + k * 64 + cg * 8);
            float4 w1 = *(const float4*)(sW + k * 64 + cg * 8 + 4);
            float4 x0 = *(const float4*)(sXT + k * 128 + ng * 8);
            float4 x1 = *(const float4*)(sXT + k * 128 + ng * 8 + 4);
            float xs[8] = {x0.x, x0.y, x0.z, x0.w, x1.x, x1.y, x1.z, x1.w};
#pragma unroll
            for (int r = 0; r < 8; r++) {
                accA[r].x = fmaf(xs[r], w0.x, accA[r].x);
                accA[r].y = fmaf(xs[r], w0.y, accA[r].y);
                accA[r].z = fmaf(xs[r], w0.z, accA[r].z);
                accA[r].w = fmaf(xs[r], w0.w, accA[r].w);
                accB[r].x = fmaf(xs[r], w1.x, accB[r].x);
                accB[r].y = fmaf(xs[r], w1.y, accB[r].y);
                accB[r].z = fmaf(xs[r], w1.z, accB[r].z);
                accB[r].w = fmaf(xs[r], w1.w, accB[r].w);
            }
        }
        __syncthreads();
    }

    float4 bb0 = __ldg((const float4*)bias + cg * 2);
    float4 bb1 = __ldg((const float4*)bias + cg * 2 + 1);
#pragma unroll
    for (int r = 0; r < 8; r++) {
        int gn = n0 + ng * 8 + r;
        if (gn >= n) break;
        float4 oa = accA[r], ob = accB[r];
        oa.x += bb0.x; oa.y += bb0.y; oa.z += bb0.z; oa.w += bb0.w;
        ob.x += bb1.x; ob.y += bb1.y; ob.z += bb1.z; ob.w += bb1.w;
        if (LAYER == 2) {
            oa.x = fmaxf(oa.x, 0.f); oa.y = fmaxf(oa.y, 0.f);
            oa.z = fmaxf(oa.z, 0.f); oa.w = fmaxf(oa.w, 0.f);
            ob.x = fmaxf(ob.x, 0.f); ob.y = fmaxf(ob.y, 0.f);
            ob.z = fmaxf(ob.z, 0.f); ob.w = fmaxf(ob.w, 0.f);
            __half2 h01 = __floats2half2_rn(oa.x, oa.y);
            __half2 h23 = __floats2half2_rn(oa.z, oa.w);
            __half2 h45 = __floats2half2_rn(ob.x, ob.y);
            __half2 h67 = __floats2half2_rn(ob.z, ob.w);
            int4 packed = make_int4(*(int*)&h01, *(int*)&h23, *(int*)&h45, *(int*)&h67);
            *(int4*)(g_h2 + gn * HD + cg * 8) = packed;
        } else {
            float* sp = g_sums + batch[gn] * HD + cg * 8;
            red_add_v4(sp, oa);
            red_add_v4(sp + 4, ob);
        }
    }
}

// ---------------- head ----------------
__global__ void head_kernel(const float* __restrict__ Wlin, const float* __restrict__ blin,
                            float* __restrict__ out, int g) {
    int idx = blockIdx.x * blockDim.x + threadIdx.x;
    if (idx >= g * 2) return;
    int gi = idx >> 1, c = idx & 1;
    float inv = 1.0f / fmaxf(g_cnt[gi], 1.0f);
    float acc = 0.f;
#pragma unroll
    for (int k = 0; k < HD; k++)
        acc = fmaf(g_sums[gi * HD + k], Wlin[k * 2 + c], acc);
    out[idx] = fmaf(acc, inv, blin[c]);
}

extern "C" void kernel_launch(void* const* d_in, const int* in_sizes, int n_in,
                              void* d_out, int out_size) {
    const float* x      = (const float*)d_in[0];
    const int*   ei     = (const int*)d_in[1];
    const int*   batch  = (const int*)d_in[2];
    const float* ew     = (const float*)d_in[3];
    const float* W1rel  = (const float*)d_in[4];
    const float* b1     = (const float*)d_in[5];
    const float* W1root = (const float*)d_in[6];
    const float* W2rel  = (const float*)d_in[7];
    const float* b2     = (const float*)d_in[8];
    const float* W2root = (const float*)d_in[9];
    const float* W3rel  = (const float*)d_in[10];
    const float* b3     = (const float*)d_in[11];
    const float* W3root = (const float*)d_in[12];
    const float* Wlin   = (const float*)d_in[13];
    const float* blin   = (const float*)d_in[14];

    int N = in_sizes[0];        // x is [N,1]
    int E = in_sizes[3];        // edge_weight is [E]
    int G = out_size / 2;

    const int* src = ei;
    const int* dst = ei + E;
    float* out = (float*)d_out;

    init_kernel<<<256, 256>>>(N, G);
    hist_kernel<<<(E / 4 + 256) / 256, 256>>>(dst, E);
    offs_kernel<<<(N + 255) / 256, 256>>>(N);
    fill_kernel<<<(E / 8 + 256) / 256, 256>>>(src, dst, ew, E);

    layer1_kernel<<<(N * 32 + 255) / 256, 256>>>(x, batch, W1rel, b1, W1root, N);
    aggH_kernel<2><<<(N * 32 + 255) / 256, 256>>>(N);
    gemm_kernel<2><<<(N + 127) / 128, 128>>>(W2rel, W2root, b2, batch, N);
    aggH_kernel<3><<<(N * 32 + 255) / 256, 256>>>(N);
    gemm_kernel<3><<<(N + 127) / 128, 128>>>(W3rel, W3root, b3, batch, N);
    head_kernel<<<(G * 2 + 255) / 256, 256>>>(Wlin, blin, out, G);
}